// round 9
// baseline (speedup 1.0000x reference)
#include <cuda_runtime.h>

// LIF neuron scan: T=8, leaky integrate + threshold + reset-by-subtraction.
// x: [T, N] fp32, N = 32*128*32*32 = 4,194,304 (N8 = 524,288 float4-pairs).
// HBM-bound streaming kernel (268 MB irreducible minus L2 write absorption).
//
// R5: 2 consecutive float4s (32B) per thread per timestep, default cache
// policy (hints were neutral/negative in R2/R4). Per timestep: 2 back-to-back
// LDG.128 then 2 back-to-back STG.128 -> longer same-direction DRAM runs,
// 2x MLP per thread vs R1, half the threads (less index ALU), while keeping
// regs moderate (unlike R2's 8-deep batch that cost occupancy).

#define T_STEPS 8
#define N_ELEM  (32 * 128 * 32 * 32)
#define N4      (N_ELEM / 4)
#define N8      (N4 / 2)                 // pairs of float4

__global__ __launch_bounds__(256) void lif_kernel(
    const float4* __restrict__ x,
    const float*  __restrict__ vth_ptr,
    float4*       __restrict__ out)
{
    int pid = blockIdx.x * blockDim.x + threadIdx.x;   // pair index
    // lane-consecutive pairs: thread handles float4s (2*pid, 2*pid+1)
    int idx = pid * 2;

    // no-grad clamp: relu(Vth - bound) + bound
    float Vth = vth_ptr[0];
    Vth = fmaxf(Vth - 0.0005f, 0.0f) + 0.0005f;

    const float beta = 0.9512294531f;   // fp32 nearest to exp(-0.05)
    const float omb  = 1.0f - beta;
    const float thr  = 0.3f * Vth;
    const float sval = Vth * 20.0f;     // Vth / DELTA_T

    float a0 = 0.f, a1 = 0.f, a2 = 0.f, a3 = 0.f;   // mem for float4 #0
    float b0 = 0.f, b1 = 0.f, b2 = 0.f, b3 = 0.f;   // mem for float4 #1

#pragma unroll
    for (int t = 0; t < T_STEPS; t++) {
        size_t base = (size_t)t * N4 + idx;
        float4 xa = x[base];
        float4 xb = x[base + 1];

        a0 = beta * a0 + omb * xa.x;
        a1 = beta * a1 + omb * xa.y;
        a2 = beta * a2 + omb * xa.z;
        a3 = beta * a3 + omb * xa.w;
        b0 = beta * b0 + omb * xb.x;
        b1 = beta * b1 + omb * xb.y;
        b2 = beta * b2 + omb * xb.z;
        b3 = beta * b3 + omb * xb.w;

        float4 oa, ob;
        if (a0 >= thr) { oa.x = sval; a0 -= Vth; } else { oa.x = 0.f; }
        if (a1 >= thr) { oa.y = sval; a1 -= Vth; } else { oa.y = 0.f; }
        if (a2 >= thr) { oa.z = sval; a2 -= Vth; } else { oa.z = 0.f; }
        if (a3 >= thr) { oa.w = sval; a3 -= Vth; } else { oa.w = 0.f; }
        if (b0 >= thr) { ob.x = sval; b0 -= Vth; } else { ob.x = 0.f; }
        if (b1 >= thr) { ob.y = sval; b1 -= Vth; } else { ob.y = 0.f; }
        if (b2 >= thr) { ob.z = sval; b2 -= Vth; } else { ob.z = 0.f; }
        if (b3 >= thr) { ob.w = sval; b3 -= Vth; } else { ob.w = 0.f; }

        out[base]     = oa;
        out[base + 1] = ob;
    }
}

extern "C" void kernel_launch(void* const* d_in, const int* in_sizes, int n_in,
                              void* d_out, int out_size) {
    const float4* x   = (const float4*)d_in[0];
    const float*  vth = (const float*)d_in[1];
    float4*       out = (float4*)d_out;

    lif_kernel<<<N8 / 256, 256>>>(x, vth, out);   // 2048 blocks
}

// round 10
// speedup vs baseline: 1.5138x; 1.5138x over previous
#include <cuda_runtime.h>

// LIF neuron scan: T=8, leaky integrate + threshold + reset-by-subtraction.
// x: [T, N] fp32, N = 32*128*32*32 = 4,194,304 (N4 = 1,048,576 float4s).
// HBM-bound streaming kernel. Plateau analysis: R1 shape (one float4 per
// thread, unit stride, interleaved load->scan->store) is the best structure;
// batching/hints/persistence/widening all regressed or were neutral.
//
// R6: R1 body with micro-cleanups:
//  - int32/pointer-bump addressing (no 64-bit IMAD chain ahead of each LDG;
//    timestep stride is the compile-time constant N4 float4s)
//  - block=512 (2048 CTAs: same occupancy, less launch/tail granularity)

#define T_STEPS 8
#define N_ELEM  (32 * 128 * 32 * 32)
#define N4      (N_ELEM / 4)
#define THREADS 512

__global__ __launch_bounds__(THREADS) void lif_kernel(
    const float4* __restrict__ x,
    const float*  __restrict__ vth_ptr,
    float4*       __restrict__ out)
{
    int idx = blockIdx.x * THREADS + threadIdx.x;

    const float4* __restrict__ xp = x + idx;
    float4*       __restrict__ op = out + idx;

    // no-grad clamp: relu(Vth - bound) + bound
    float Vth = vth_ptr[0];
    Vth = fmaxf(Vth - 0.0005f, 0.0f) + 0.0005f;

    const float beta = 0.9512294531f;   // fp32 nearest to exp(-0.05)
    const float omb  = 1.0f - beta;
    const float thr  = 0.3f * Vth;
    const float sval = Vth * 20.0f;     // Vth / DELTA_T

    float mx = 0.f, my = 0.f, mz = 0.f, mw = 0.f;

#pragma unroll
    for (int t = 0; t < T_STEPS; t++, xp += N4, op += N4) {
        float4 xt = *xp;

        mx = beta * mx + omb * xt.x;
        my = beta * my + omb * xt.y;
        mz = beta * mz + omb * xt.z;
        mw = beta * mw + omb * xt.w;

        float4 o;
        if (mx >= thr) { o.x = sval; mx -= Vth; } else { o.x = 0.f; }
        if (my >= thr) { o.y = sval; my -= Vth; } else { o.y = 0.f; }
        if (mz >= thr) { o.z = sval; mz -= Vth; } else { o.z = 0.f; }
        if (mw >= thr) { o.w = sval; mw -= Vth; } else { o.w = 0.f; }

        *op = o;
    }
}

extern "C" void kernel_launch(void* const* d_in, const int* in_sizes, int n_in,
                              void* d_out, int out_size) {
    const float4* x   = (const float4*)d_in[0];
    const float*  vth = (const float*)d_in[1];
    float4*       out = (float4*)d_out;

    lif_kernel<<<N4 / THREADS, THREADS>>>(x, vth, out);   // 2048 blocks x 512
}

// round 11
// speedup vs baseline: 1.5181x; 1.0028x over previous
#include <cuda_runtime.h>

// LIF neuron scan: T=8, leaky integrate + threshold + reset-by-subtraction.
// x: [T, N] fp32, N = 32*128*32*32 = 4,194,304 (N4 = 1,048,576 float4s).
//
// FINAL (R7): converged HBM-bound streaming kernel.
// Evidence across 6 structural variants (batched loads, persistent grid,
// cache hints, 2-wide threads, block=512): ncu kernel time is pinned at
// 36.0-36.9us <=> ~5.9TB/s DRAM + ~54MB L2 write absorption for every
// unit-stride, occupancy>=59% configuration. This is the effective mixed
// read/write DRAM ceiling; traffic (134MB read + 134MB fp32 write) is
// irreducible. Config below = best-measured grid (4096x256, R1) + cleanest
// body (pointer-bump, R6).

#define T_STEPS 8
#define N_ELEM  (32 * 128 * 32 * 32)
#define N4      (N_ELEM / 4)
#define THREADS 256

__global__ __launch_bounds__(THREADS) void lif_kernel(
    const float4* __restrict__ x,
    const float*  __restrict__ vth_ptr,
    float4*       __restrict__ out)
{
    int idx = blockIdx.x * THREADS + threadIdx.x;

    const float4* __restrict__ xp = x + idx;
    float4*       __restrict__ op = out + idx;

    // no-grad clamp: relu(Vth - bound) + bound
    float Vth = vth_ptr[0];
    Vth = fmaxf(Vth - 0.0005f, 0.0f) + 0.0005f;

    const float beta = 0.9512294531f;   // fp32 nearest to exp(-0.05)
    const float omb  = 1.0f - beta;
    const float thr  = 0.3f * Vth;      // ALPHA * Vth
    const float sval = Vth * 20.0f;     // Vth / DELTA_T

    float mx = 0.f, my = 0.f, mz = 0.f, mw = 0.f;

#pragma unroll
    for (int t = 0; t < T_STEPS; t++, xp += N4, op += N4) {
        float4 xt = *xp;

        mx = beta * mx + omb * xt.x;
        my = beta * my + omb * xt.y;
        mz = beta * mz + omb * xt.z;
        mw = beta * mw + omb * xt.w;

        float4 o;
        if (mx >= thr) { o.x = sval; mx -= Vth; } else { o.x = 0.f; }
        if (my >= thr) { o.y = sval; my -= Vth; } else { o.y = 0.f; }
        if (mz >= thr) { o.z = sval; mz -= Vth; } else { o.z = 0.f; }
        if (mw >= thr) { o.w = sval; mw -= Vth; } else { o.w = 0.f; }

        *op = o;
    }
}

extern "C" void kernel_launch(void* const* d_in, const int* in_sizes, int n_in,
                              void* d_out, int out_size) {
    const float4* x   = (const float4*)d_in[0];
    const float*  vth = (const float*)d_in[1];
    float4*       out = (float4*)d_out;

    lif_kernel<<<N4 / THREADS, THREADS>>>(x, vth, out);   // 4096 blocks x 256
}